// round 8
// baseline (speedup 1.0000x reference)
#include <cuda_runtime.h>
#include <cuda_pipeline.h>
#include <cstdint>

#define EPS 1e-10f
#define P_NODES (1u << 20)          // nodes per tree (H*W)
#define THREADS 256
#define MAX_TREES 4
#define T0 2048                     // resolved by K2 (in-block doubling)

// Per-node record written once by K1, read-only afterwards:
//   .x = __float_as_uint(contrib), .y = parent index
__device__ uint2 g_rec[(size_t)MAX_TREES * P_NODES];

// ---------------------------------------------------------------------------
// K1: contrib[i] = (x[i] - x[parent[i]]) * sigmoid(w . feats(attrs[i]) + b)
// cp.async double-buffered staging, 2 chunks of 256 nodes per block.
// ---------------------------------------------------------------------------
__global__ __launch_bounds__(THREADS)
void k1_contrib(const float* __restrict__ x,
                const float* __restrict__ weight,   // (N,17,1)
                const float* __restrict__ bias,     // (N,1)
                const float* __restrict__ attrs,    // (T,P,15)
                const int*   __restrict__ parents,  // (T,P)
                int N)
{
    __shared__ float stage[2][THREADS * 15];        // 2 x 15 KB
    const int bpt   = P_NODES / (THREADS * 2);      // 2048 blocks per tree
    const int tree  = blockIdx.x / bpt;
    const int c0    = (blockIdx.x - tree * bpt) * 2;    // first chunk index
    const size_t tb = (size_t)tree * P_NODES;

    const int n = tree % N;
    float wv[17];
    #pragma unroll
    for (int i = 0; i < 17; i++) wv[i] = __ldg(&weight[n * 17 + i]);
    const float bv = __ldg(&bias[n]);

    const int NF4 = (THREADS * 15) / 4;             // 960 float4 per chunk
    const float4* abase = (const float4*)(attrs + tb * 15);

    // Kick off async copies for both chunks (one commit group each)
    #pragma unroll
    for (int j = 0; j < 2; j++) {
        const float4* src = abase + (size_t)(c0 + j) * NF4;
        float4* dst = (float4*)stage[j];
        #pragma unroll
        for (int k = 0; k < 4; k++) {
            const int idx = k * THREADS + threadIdx.x;
            if (idx < NF4) __pipeline_memcpy_async(&dst[idx], &src[idx], 16);
        }
        __pipeline_commit();
    }

    // Scalar per-node loads issued early (overlap with cp.async)
    int   p0v, p1v;
    float x0v, x1v;
    {
        const int n0 = c0 * THREADS + threadIdx.x;
        const int n1 = n0 + THREADS;
        p0v = __ldg(&parents[tb + n0]);  x0v = __ldg(&x[tb + n0]);
        p1v = __ldg(&parents[tb + n1]);  x1v = __ldg(&x[tb + n1]);
    }

    #pragma unroll
    for (int j = 0; j < 2; j++) {
        __pipeline_wait_prior(1 - j);               // buf j ready
        __syncthreads();

        const float* a = &stage[j][threadIdx.x * 15];   // stride 15: conflict-free
        float lin = bv;
        lin += a[0]*wv[0] + a[1]*wv[1] + a[2]*wv[2] + a[3]*wv[3] + a[4]*wv[4];
        #pragma unroll
        for (int c = 0; c < 9; c++)
            lin += __logf(fabsf(a[6 + c]) + EPS) * wv[5 + c];
        lin += __fdividef(__fsqrt_rn(a[7]), __fsqrt_rn(a[6]) + EPS) * wv[14];
        float sa, ca;
        __sincosf(a[5], &sa, &ca);
        lin += ca * wv[15] + sa * wv[16];
        const float score = __fdividef(1.0f, 1.0f + __expf(-lin));

        const int   node = (c0 + j) * THREADS + threadIdx.x;
        const int   p    = j ? p1v : p0v;
        const float xv   = j ? x1v : x0v;
        const float diff = (p == node) ? xv : (xv - __ldg(&x[tb + p]));

        const uint2 rec = make_uint2(__float_as_uint(diff * score), (unsigned)p);
        __stcg((uint2*)&g_rec[tb + node], rec);     // bypass L1; walks read via L2
    }
}

// ---------------------------------------------------------------------------
// K2: resolve nodes [0, T0) per tree via pointer doubling in shared memory.
// ---------------------------------------------------------------------------
__global__ __launch_bounds__(1024)
void k2_base(float* __restrict__ out)
{
    __shared__ float v0[T0 + 1], v1[T0 + 1];
    __shared__ int   p0[T0 + 1], p1[T0 + 1];

    const size_t tb = (size_t)blockIdx.x * P_NODES;

    for (int i = threadIdx.x; i <= T0; i += 1024) {
        if (i < T0) {
            const uint2 r = g_rec[tb + i];
            v0[i] = __uint_as_float(r.x);
            p0[i] = (i == 0 || (int)r.y == i) ? T0 : (int)r.y;  // root -> sentinel
        } else {
            v0[i] = 0.0f;
            p0[i] = T0;
        }
    }
    __syncthreads();

    float* cv = v0; float* nv = v1;
    int*   cp = p0; int*   np = p1;
    #pragma unroll 1
    for (int it = 0; it < 11; it++) {               // 2^11 >= T0
        for (int i = threadIdx.x; i <= T0; i += 1024) {
            const int pp = cp[i];
            nv[i] = cv[i] + cv[pp];
            np[i] = cp[pp];
        }
        __syncthreads();
        float* tv = cv; cv = nv; nv = tv;
        int*   tp = cp; cp = np; np = tp;
    }

    for (int i = threadIdx.x; i < T0; i += 1024)
        out[tb + i] = cv[i];
}

// ---------------------------------------------------------------------------
// W1: [2048, 128K) walk to < 2048. 4 interleaved chains per thread.
// ---------------------------------------------------------------------------
__global__ __launch_bounds__(THREADS)
void walk_low(float* __restrict__ out, int blocks_per_tree)
{
    const int tree = blockIdx.x / blocks_per_tree;
    const int lb   = blockIdx.x - tree * blocks_per_tree;
    const size_t tb = (size_t)tree * P_NODES;
    const int n0 = T0 + lb * (THREADS * 4) + threadIdx.x;

    int   node[4];
    float sum[4];
    unsigned q[4];
    #pragma unroll
    for (int c = 0; c < 4; c++) {
        node[c] = n0 + c * THREADS;
        const uint2 r = __ldg(&g_rec[tb + node[c]]);
        sum[c] = __uint_as_float(r.x);
        q[c]   = r.y;
    }

    #pragma unroll 1
    for (;;) {
        bool any = false;
        #pragma unroll
        for (int c = 0; c < 4; c++) {
            if (q[c] >= (unsigned)T0) {
                const uint2 r = __ldg(&g_rec[tb + q[c]]);
                sum[c] += __uint_as_float(r.x);
                q[c] = r.y;
                any = true;
            }
        }
        if (!any) break;
    }

    #pragma unroll
    for (int c = 0; c < 4; c++)
        out[tb + node[c]] = sum[c] + __ldg(&out[tb + q[c]]);
}

// ---------------------------------------------------------------------------
// W2/W3: tier [BASE, HIGH) walk to < LOW, 4 interleaved chains per thread.
// ---------------------------------------------------------------------------
template <int LOW, int BASE>
__global__ __launch_bounds__(THREADS)
void k_walk4(float* __restrict__ out, int blocks_per_tree)
{
    const int tree = blockIdx.x / blocks_per_tree;
    const int lb   = blockIdx.x - tree * blocks_per_tree;
    const size_t tb = (size_t)tree * P_NODES;
    const int n0 = BASE + lb * (THREADS * 4) + threadIdx.x;

    int   node[4];
    float sum[4];
    unsigned q[4];
    #pragma unroll
    for (int c = 0; c < 4; c++) {
        node[c] = n0 + c * THREADS;
        const uint2 r = __ldg(&g_rec[tb + node[c]]);
        sum[c] = __uint_as_float(r.x);
        q[c]   = r.y;
    }

    #pragma unroll 1
    for (;;) {
        bool any = false;
        #pragma unroll
        for (int c = 0; c < 4; c++) {
            if (q[c] >= (unsigned)LOW) {
                const uint2 r = __ldg(&g_rec[tb + q[c]]);
                sum[c] += __uint_as_float(r.x);
                q[c] = r.y;
                any = true;
            }
        }
        if (!any) break;
    }

    #pragma unroll
    for (int c = 0; c < 4; c++)
        out[tb + node[c]] = sum[c] + __ldg(&out[tb + q[c]]);
}

// ---------------------------------------------------------------------------
extern "C" void kernel_launch(void* const* d_in, const int* in_sizes, int n_in,
                              void* d_out, int out_size)
{
    const float* x       = (const float*)d_in[0];   // (B,N,H,W) f32
    const float* weight  = (const float*)d_in[1];   // (N,17,1)  f32
    const float* bias    = (const float*)d_in[2];   // (N,1)     f32
    const float* attrs   = (const float*)d_in[3];   // (B,N,P,15) f32
    const int*   parents = (const int*)d_in[4];     // (B,N,P)   i32
    float* out = (float*)d_out;

    const int n_trees = in_sizes[0] / (int)P_NODES; // B*N = 4
    const int N       = in_sizes[1] / 17;

    // K1: streaming contrib pass (cp.async double-buffered, 2 chunks/block)
    k1_contrib<<<n_trees * (P_NODES / (THREADS * 2)), THREADS>>>(x, weight, bias, attrs, parents, N);
    // K2: base tier via in-block pointer doubling
    k2_base<<<n_trees, 1024>>>(out);

    // W1: [2048, 131072) -> walk to < 2048 (r=64, E~3.2)
    {
        const int bpt = (131072 - T0) / (THREADS * 4);           // 126
        walk_low<<<n_trees * bpt, THREADS>>>(out, bpt);
    }
    // W2: [131072, 524288) -> walk to < 131072 (r=4, E~0.85)
    {
        const int bpt = (524288 - 131072) / (THREADS * 4);       // 384
        k_walk4<131072, 131072><<<n_trees * bpt, THREADS>>>(out, bpt);
    }
    // W3: [524288, 1M) -> walk to < 524288 (r=2, E~0.39)
    {
        const int bpt = ((int)P_NODES - 524288) / (THREADS * 4); // 512
        k_walk4<524288, 524288><<<n_trees * bpt, THREADS>>>(out, bpt);
    }
}

// round 9
// speedup vs baseline: 1.1011x; 1.1011x over previous
#include <cuda_runtime.h>
#include <cuda_pipeline.h>
#include <cstdint>

#define EPS 1e-10f
#define P_NODES (1u << 20)          // nodes per tree (H*W)
#define THREADS 256
#define MAX_TREES 4
#define T0 2048                     // resolved by K2 (in-block doubling)

// Per-node record written once by K1, read-only afterwards:
//   .x = __float_as_uint(contrib), .y = parent index
__device__ uint2 g_rec[(size_t)MAX_TREES * P_NODES];

// ---------------------------------------------------------------------------
// K1: contrib[i] = (x[i] - x[parent[i]]) * sigmoid(w . feats(attrs[i]) + b)
// cp.async double-buffered staging, 2 chunks of 256 nodes per block.
// ---------------------------------------------------------------------------
__global__ __launch_bounds__(THREADS)
void k1_contrib(const float* __restrict__ x,
                const float* __restrict__ weight,   // (N,17,1)
                const float* __restrict__ bias,     // (N,1)
                const float* __restrict__ attrs,    // (T,P,15)
                const int*   __restrict__ parents,  // (T,P)
                int N)
{
    __shared__ float stage[2][THREADS * 15];        // 2 x 15 KB
    const int bpt   = P_NODES / (THREADS * 2);      // 2048 blocks per tree
    const int tree  = blockIdx.x / bpt;
    const int c0    = (blockIdx.x - tree * bpt) * 2;
    const size_t tb = (size_t)tree * P_NODES;

    const int n = tree % N;
    float wv[17];
    #pragma unroll
    for (int i = 0; i < 17; i++) wv[i] = __ldg(&weight[n * 17 + i]);
    const float bv = __ldg(&bias[n]);

    const int NF4 = (THREADS * 15) / 4;             // 960 float4 per chunk
    const float4* abase = (const float4*)(attrs + tb * 15);

    #pragma unroll
    for (int j = 0; j < 2; j++) {
        const float4* src = abase + (size_t)(c0 + j) * NF4;
        float4* dst = (float4*)stage[j];
        #pragma unroll
        for (int k = 0; k < 4; k++) {
            const int idx = k * THREADS + threadIdx.x;
            if (idx < NF4) __pipeline_memcpy_async(&dst[idx], &src[idx], 16);
        }
        __pipeline_commit();
    }

    int   p0v, p1v;
    float x0v, x1v;
    {
        const int n0 = c0 * THREADS + threadIdx.x;
        const int n1 = n0 + THREADS;
        p0v = __ldg(&parents[tb + n0]);  x0v = __ldg(&x[tb + n0]);
        p1v = __ldg(&parents[tb + n1]);  x1v = __ldg(&x[tb + n1]);
    }

    #pragma unroll
    for (int j = 0; j < 2; j++) {
        __pipeline_wait_prior(1 - j);
        __syncthreads();

        const float* a = &stage[j][threadIdx.x * 15];
        float lin = bv;
        lin += a[0]*wv[0] + a[1]*wv[1] + a[2]*wv[2] + a[3]*wv[3] + a[4]*wv[4];
        #pragma unroll
        for (int c = 0; c < 9; c++)
            lin += __logf(fabsf(a[6 + c]) + EPS) * wv[5 + c];
        lin += __fdividef(__fsqrt_rn(a[7]), __fsqrt_rn(a[6]) + EPS) * wv[14];
        float sa, ca;
        __sincosf(a[5], &sa, &ca);
        lin += ca * wv[15] + sa * wv[16];
        const float score = __fdividef(1.0f, 1.0f + __expf(-lin));

        const int   node = (c0 + j) * THREADS + threadIdx.x;
        const int   p    = j ? p1v : p0v;
        const float xv   = j ? x1v : x0v;
        const float diff = (p == node) ? xv : (xv - __ldg(&x[tb + p]));

        const uint2 rec = make_uint2(__float_as_uint(diff * score), (unsigned)p);
        __stcg((uint2*)&g_rec[tb + node], rec);
    }
}

// ---------------------------------------------------------------------------
// K2: resolve nodes [0, T0) per tree via pointer doubling in shared memory.
// PDL: triggers successor at entry; syncs on K1 before reading rec.
// ---------------------------------------------------------------------------
__global__ __launch_bounds__(1024)
void k2_base(float* __restrict__ out)
{
    cudaTriggerProgrammaticLaunchCompletion();      // let W1 start its walk now
    cudaGridDependencySynchronize();                // rec must be final (K1 done)

    __shared__ float v0[T0 + 1], v1[T0 + 1];
    __shared__ int   p0[T0 + 1], p1[T0 + 1];

    const size_t tb = (size_t)blockIdx.x * P_NODES;

    for (int i = threadIdx.x; i <= T0; i += 1024) {
        if (i < T0) {
            const uint2 r = g_rec[tb + i];
            v0[i] = __uint_as_float(r.x);
            p0[i] = (i == 0 || (int)r.y == i) ? T0 : (int)r.y;  // root -> sentinel
        } else {
            v0[i] = 0.0f;
            p0[i] = T0;
        }
    }
    __syncthreads();

    float* cv = v0; float* nv = v1;
    int*   cp = p0; int*   np = p1;
    #pragma unroll 1
    for (int it = 0; it < 11; it++) {               // 2^11 >= T0
        for (int i = threadIdx.x; i <= T0; i += 1024) {
            const int pp = cp[i];
            nv[i] = cv[i] + cv[pp];
            np[i] = cp[pp];
        }
        __syncthreads();
        float* tv = cv; cv = nv; nv = tv;
        int*   tp = cp; cp = np; np = tp;
    }

    for (int i = threadIdx.x; i < T0; i += 1024)
        out[tb + i] = cv[i];
}

// ---------------------------------------------------------------------------
// W1: [2048, 128K) walk to < 2048. 4 interleaved chains per thread.
// Walk reads only rec (final since K1). Epilogue waits on K2's out[0,T0).
// ---------------------------------------------------------------------------
__global__ __launch_bounds__(THREADS)
void walk_low(float* __restrict__ out, int blocks_per_tree)
{
    cudaTriggerProgrammaticLaunchCompletion();      // let W2 start its walk now

    const int tree = blockIdx.x / blocks_per_tree;
    const int lb   = blockIdx.x - tree * blocks_per_tree;
    const size_t tb = (size_t)tree * P_NODES;
    const int n0 = T0 + lb * (THREADS * 4) + threadIdx.x;

    int   node[4];
    float sum[4];
    unsigned q[4];
    #pragma unroll
    for (int c = 0; c < 4; c++) {
        node[c] = n0 + c * THREADS;
        const uint2 r = __ldg(&g_rec[tb + node[c]]);
        sum[c] = __uint_as_float(r.x);
        q[c]   = r.y;
    }

    #pragma unroll 1
    for (;;) {
        bool any = false;
        #pragma unroll
        for (int c = 0; c < 4; c++) {
            if (q[c] >= (unsigned)T0) {
                const uint2 r = __ldg(&g_rec[tb + q[c]]);
                sum[c] += __uint_as_float(r.x);
                q[c] = r.y;
                any = true;
            }
        }
        if (!any) break;
    }

    cudaGridDependencySynchronize();                // out[0,T0) ready (K2 done)
    #pragma unroll
    for (int c = 0; c < 4; c++)
        out[tb + node[c]] = sum[c] + __ldg(&out[tb + q[c]]);
}

// ---------------------------------------------------------------------------
// W2/W3: tier walk to < LOW, 2 interleaved chains per thread (full grid).
// Walk phase depends only on rec; epilogue waits on previous tier via PDL.
// ---------------------------------------------------------------------------
template <int LOW, int BASE>
__global__ __launch_bounds__(THREADS)
void k_walk2(float* __restrict__ out, int blocks_per_tree)
{
    cudaTriggerProgrammaticLaunchCompletion();      // let next tier start its walk

    const int tree = blockIdx.x / blocks_per_tree;
    const int lb   = blockIdx.x - tree * blocks_per_tree;
    const size_t tb = (size_t)tree * P_NODES;
    const int na = BASE + lb * (THREADS * 2) + threadIdx.x;
    const int nb = na + THREADS;

    uint2 ra = __ldg(&g_rec[tb + na]);
    uint2 rb = __ldg(&g_rec[tb + nb]);
    float sa = __uint_as_float(ra.x);
    float sb = __uint_as_float(rb.x);
    unsigned qa = ra.y, qb = rb.y;

    #pragma unroll 1
    while (qa >= (unsigned)LOW || qb >= (unsigned)LOW) {
        if (qa >= (unsigned)LOW) {
            const uint2 r = __ldg(&g_rec[tb + qa]);
            sa += __uint_as_float(r.x);
            qa = r.y;
        }
        if (qb >= (unsigned)LOW) {
            const uint2 r = __ldg(&g_rec[tb + qb]);
            sb += __uint_as_float(r.x);
            qb = r.y;
        }
    }

    cudaGridDependencySynchronize();                // out[< LOW] ready (prev tier done)
    sa += __ldg(&out[tb + qa]);
    sb += __ldg(&out[tb + qb]);
    out[tb + na] = sa;
    out[tb + nb] = sb;
}

// ---------------------------------------------------------------------------
template <typename F, typename... Args>
static inline void launch_pdl(F f, int grid, int block, Args... args)
{
    cudaLaunchConfig_t cfg = {};
    cfg.gridDim  = dim3((unsigned)grid, 1, 1);
    cfg.blockDim = dim3((unsigned)block, 1, 1);
    cudaLaunchAttribute attr[1];
    attr[0].id = cudaLaunchAttributeProgrammaticStreamSerialization;
    attr[0].val.programmaticStreamSerializationAllowed = 1;
    cfg.attrs = attr;
    cfg.numAttrs = 1;
    cudaLaunchKernelEx(&cfg, f, args...);
}

extern "C" void kernel_launch(void* const* d_in, const int* in_sizes, int n_in,
                              void* d_out, int out_size)
{
    const float* x       = (const float*)d_in[0];   // (B,N,H,W) f32
    const float* weight  = (const float*)d_in[1];   // (N,17,1)  f32
    const float* bias    = (const float*)d_in[2];   // (N,1)     f32
    const float* attrs   = (const float*)d_in[3];   // (B,N,P,15) f32
    const int*   parents = (const int*)d_in[4];     // (B,N,P)   i32
    float* out = (float*)d_out;

    const int n_trees = in_sizes[0] / (int)P_NODES; // B*N = 4
    const int N       = in_sizes[1] / 17;

    // K1: streaming contrib pass (normal launch; must fully complete first)
    k1_contrib<<<n_trees * (P_NODES / (THREADS * 2)), THREADS>>>(x, weight, bias, attrs, parents, N);

    // K2 + walk tiers: PDL chain — walks overlap, epilogues serialize.
    launch_pdl(k2_base, n_trees, 1024, out);
    {   // W1: [2048, 131072) -> < 2048
        const int bpt = (131072 - T0) / (THREADS * 4);           // 126
        launch_pdl(walk_low, n_trees * bpt, THREADS, out, bpt);
    }
    {   // W2: [131072, 524288) -> < 131072
        const int bpt = (524288 - 131072) / (THREADS * 2);       // 768
        launch_pdl(k_walk2<131072, 131072>, n_trees * bpt, THREADS, out, bpt);
    }
    {   // W3: [524288, 1M) -> < 524288
        const int bpt = ((int)P_NODES - 524288) / (THREADS * 2); // 1024
        launch_pdl(k_walk2<524288, 524288>, n_trees * bpt, THREADS, out, bpt);
    }
}